// round 1
// baseline (speedup 1.0000x reference)
#include <cuda_runtime.h>
#include <math.h>

#define TILE      32
#define HALO      5
#define RAW       (TILE + 2*HALO)   /* 42 */
#define RAWP      43                /* odd pitch -> conflict-free horizontal reads */
#define HP        33                /* odd pitch -> conflict-free vertical reads  */
#define NTHREADS  256

// Per-block partial sums (deterministic: each block writes exactly one slot).
__device__ float g_blockSums[65536];

// Normalized 1D Gaussian, size 11, sigma 1.5 (matches cv2.getGaussianKernel).
// Returned as compile-time constant so ptxas emits FFMA-imm (rt_SMSP=1).
__device__ __forceinline__ float gw(int t) {
    constexpr float G[11] = {
        0.00102838f, 0.00759876f, 0.03600077f, 0.10936069f, 0.21300553f,
        0.26601172f,
        0.21300553f, 0.10936069f, 0.03600077f, 0.00759876f, 0.00102838f };
    return G[t];
}

__global__ __launch_bounds__(NTHREADS)
void ssim_tile_kernel(const float* __restrict__ img1,
                      const float* __restrict__ img2,
                      int W, int H)
{
    __shared__ float sx[RAW][RAWP];
    __shared__ float sy[RAW][RAWP];
    __shared__ float hs[5][RAW][HP];   // horizontally blurred: x, y, xx, yy, xy
    __shared__ float wsum[NTHREADS / 32];

    const int tid = threadIdx.x;
    const int bx = blockIdx.x * TILE;
    const int by = blockIdx.y * TILE;

    // ---------------- load raw tile with replicate ("edge") padding ----------------
    for (int i = tid; i < RAW * RAW; i += NTHREADS) {
        int r = i / RAW;
        int c = i - r * RAW;
        int gy = by - HALO + r; gy = gy < 0 ? 0 : (gy >= H ? H - 1 : gy);
        int gx = bx - HALO + c; gx = gx < 0 ? 0 : (gx >= W ? W - 1 : gx);
        size_t idx = (size_t)gy * (size_t)W + (size_t)gx;
        sx[r][c] = img1[idx];
        sy[r][c] = img2[idx];
    }
    __syncthreads();

    // ---------------- horizontal pass: 42 rows x 8 groups of 4 output cols ----------
    // Group g covers output cols 4g..4g+3, consuming raw cols 4g..4g+13.
    for (int i = tid; i < RAW * 8; i += NTHREADS) {
        const int r = i >> 3;
        const int g = (i & 7) * 4;

        float ax[4]  = {0.f, 0.f, 0.f, 0.f};
        float ay[4]  = {0.f, 0.f, 0.f, 0.f};
        float axx[4] = {0.f, 0.f, 0.f, 0.f};
        float ayy[4] = {0.f, 0.f, 0.f, 0.f};
        float axy[4] = {0.f, 0.f, 0.f, 0.f};

        #pragma unroll
        for (int k = 0; k < 14; k++) {
            const float vx = sx[r][g + k];
            const float vy = sy[r][g + k];
            const float vxx = vx * vx;
            const float vyy = vy * vy;
            const float vxy = vx * vy;
            #pragma unroll
            for (int o = 0; o < 4; o++) {
                const int t = k - o;
                if (t >= 0 && t < 11) {
                    ax[o]  = fmaf(vx,  gw(t), ax[o]);
                    ay[o]  = fmaf(vy,  gw(t), ay[o]);
                    axx[o] = fmaf(vxx, gw(t), axx[o]);
                    ayy[o] = fmaf(vyy, gw(t), ayy[o]);
                    axy[o] = fmaf(vxy, gw(t), axy[o]);
                }
            }
        }
        #pragma unroll
        for (int o = 0; o < 4; o++) {
            hs[0][r][g + o] = ax[o];
            hs[1][r][g + o] = ay[o];
            hs[2][r][g + o] = axx[o];
            hs[3][r][g + o] = ayy[o];
            hs[4][r][g + o] = axy[o];
        }
    }
    __syncthreads();

    // ---------------- vertical pass + SSIM: 32 cols x 8 row-groups of 4 rows --------
    float lsum = 0.f;
    {
        const int c  = tid & 31;
        const int r0 = (tid >> 5) * 4;   // output rows r0..r0+3, using hs rows r0..r0+13

        float acc[5][4];
        #pragma unroll
        for (int ch = 0; ch < 5; ch++) {
            float s0 = 0.f, s1 = 0.f, s2 = 0.f, s3 = 0.f;
            #pragma unroll
            for (int j = 0; j < 14; j++) {
                const float v = hs[ch][r0 + j][c];
                if (j <= 10)            s0 = fmaf(v, gw(j),     s0);
                if (j >= 1 && j <= 11)  s1 = fmaf(v, gw(j - 1), s1);
                if (j >= 2 && j <= 12)  s2 = fmaf(v, gw(j - 2), s2);
                if (j >= 3)             s3 = fmaf(v, gw(j - 3), s3);
            }
            acc[ch][0] = s0; acc[ch][1] = s1; acc[ch][2] = s2; acc[ch][3] = s3;
        }

        const float C1 = 6.5025f;    // (0.01*255)^2
        const float C2 = 58.5225f;   // (0.03*255)^2
        #pragma unroll
        for (int o = 0; o < 4; o++) {
            if (by + r0 + o < H && bx + c < W) {
                const float mu1 = acc[0][o], mu2 = acc[1][o];
                const float exx = acc[2][o], eyy = acc[3][o], exy = acc[4][o];
                const float m11 = mu1 * mu1;
                const float m22 = mu2 * mu2;
                const float m12 = mu1 * mu2;
                const float s1q = exx - m11;
                const float s2q = eyy - m22;
                const float s12 = exy - m12;
                const float num = (2.f * m12 + C1) * (2.f * s12 + C2);
                const float den = (m11 + m22 + C1) * (s1q + s2q + C2);
                lsum += __fdividef(num, den);
            }
        }
    }

    // ---------------- block reduction ----------------
    #pragma unroll
    for (int off = 16; off; off >>= 1)
        lsum += __shfl_xor_sync(0xffffffffu, lsum, off);
    if ((tid & 31) == 0) wsum[tid >> 5] = lsum;
    __syncthreads();
    if (tid == 0) {
        float s = 0.f;
        #pragma unroll
        for (int w = 0; w < NTHREADS / 32; w++) s += wsum[w];
        g_blockSums[blockIdx.y * gridDim.x + blockIdx.x] = s;
    }
}

__global__ void ssim_reduce_kernel(int nb, double inv_n, float* __restrict__ out)
{
    __shared__ double sm[256];
    double acc = 0.0;
    for (int i = threadIdx.x; i < nb; i += 256)
        acc += (double)g_blockSums[i];
    sm[threadIdx.x] = acc;
    __syncthreads();
    #pragma unroll
    for (int s = 128; s; s >>= 1) {
        if (threadIdx.x < s) sm[threadIdx.x] += sm[threadIdx.x + s];
        __syncthreads();
    }
    if (threadIdx.x == 0) out[0] = (float)(sm[0] * inv_n);
}

extern "C" void kernel_launch(void* const* d_in, const int* in_sizes, int n_in,
                              void* d_out, int out_size)
{
    (void)n_in; (void)out_size;
    const float* img1 = (const float*)d_in[0];
    const float* img2 = (const float*)d_in[1];

    const long long n = (long long)in_sizes[0];
    int W = (int)(sqrt((double)n) + 0.5);
    if (W <= 0) W = 1;
    int H = (int)(n / W);

    dim3 grid((W + TILE - 1) / TILE, (H + TILE - 1) / TILE);
    ssim_tile_kernel<<<grid, NTHREADS>>>(img1, img2, W, H);

    const int nb = (int)(grid.x * grid.y);
    const double inv_n = 1.0 / ((double)H * (double)W);
    ssim_reduce_kernel<<<1, 256>>>(nb, inv_n, (float*)d_out);
}

// round 2
// speedup vs baseline: 1.0432x; 1.0432x over previous
#include <cuda_runtime.h>
#include <math.h>

#define TILE      32
#define HALO      5
#define RAW       (TILE + 2*HALO)   /* 42 */
#define RAWP      43                /* odd pitch -> conflict-free horizontal reads */
#define HP        33                /* odd pitch -> conflict-free vertical reads  */
#define NTHREADS  256

// Per-block partial sums (deterministic: each block writes exactly one slot).
__device__ float g_blockSums[65536];
__device__ unsigned int g_count = 0;

// Normalized 1D Gaussian, size 11, sigma 1.5 (matches cv2.getGaussianKernel).
// Compile-time constants so ptxas emits FFMA-imm (rt_SMSP=1).
__device__ __forceinline__ float gw(int t) {
    constexpr float G[11] = {
        0.00102838f, 0.00759876f, 0.03600077f, 0.10936069f, 0.21300553f,
        0.26601172f,
        0.21300553f, 0.10936069f, 0.03600077f, 0.00759876f, 0.00102838f };
    return G[t];
}

__global__ __launch_bounds__(NTHREADS)
void ssim_tile_kernel(const float* __restrict__ img1,
                      const float* __restrict__ img2,
                      int W, int H, int nBlocks, double inv_n,
                      float* __restrict__ out)
{
    __shared__ float sx[RAW][RAWP];
    __shared__ float sy[RAW][RAWP];
    __shared__ float hs[5][RAW][HP];   // horizontally blurred: x, y, xx, yy, xy
    __shared__ float wsum[NTHREADS / 32];
    __shared__ bool  isLast;

    const int tid = threadIdx.x;
    const int bx = blockIdx.x * TILE;
    const int by = blockIdx.y * TILE;

    // ---------------- load raw tile with replicate ("edge") padding ----------------
    for (int i = tid; i < RAW * RAW; i += NTHREADS) {
        int r = i / RAW;
        int c = i - r * RAW;
        int gy = by - HALO + r; gy = gy < 0 ? 0 : (gy >= H ? H - 1 : gy);
        int gx = bx - HALO + c; gx = gx < 0 ? 0 : (gx >= W ? W - 1 : gx);
        size_t idx = (size_t)gy * (size_t)W + (size_t)gx;
        sx[r][c] = img1[idx];
        sy[r][c] = img2[idx];
    }
    __syncthreads();

    // ---------------- horizontal pass: 42 rows x 8 groups of 4 output cols ----------
    for (int i = tid; i < RAW * 8; i += NTHREADS) {
        const int r = i >> 3;
        const int g = (i & 7) * 4;

        float ax[4]  = {0.f, 0.f, 0.f, 0.f};
        float ay[4]  = {0.f, 0.f, 0.f, 0.f};
        float axx[4] = {0.f, 0.f, 0.f, 0.f};
        float ayy[4] = {0.f, 0.f, 0.f, 0.f};
        float axy[4] = {0.f, 0.f, 0.f, 0.f};

        #pragma unroll
        for (int k = 0; k < 14; k++) {
            const float vx = sx[r][g + k];
            const float vy = sy[r][g + k];
            const float vxx = vx * vx;
            const float vyy = vy * vy;
            const float vxy = vx * vy;
            #pragma unroll
            for (int o = 0; o < 4; o++) {
                const int t = k - o;
                if (t >= 0 && t < 11) {
                    ax[o]  = fmaf(vx,  gw(t), ax[o]);
                    ay[o]  = fmaf(vy,  gw(t), ay[o]);
                    axx[o] = fmaf(vxx, gw(t), axx[o]);
                    ayy[o] = fmaf(vyy, gw(t), ayy[o]);
                    axy[o] = fmaf(vxy, gw(t), axy[o]);
                }
            }
        }
        #pragma unroll
        for (int o = 0; o < 4; o++) {
            hs[0][r][g + o] = ax[o];
            hs[1][r][g + o] = ay[o];
            hs[2][r][g + o] = axx[o];
            hs[3][r][g + o] = ayy[o];
            hs[4][r][g + o] = axy[o];
        }
    }
    __syncthreads();

    // ---------------- vertical pass + SSIM: 32 cols x 8 row-groups of 4 rows --------
    float lsum = 0.f;
    {
        const int c  = tid & 31;
        const int r0 = (tid >> 5) * 4;   // output rows r0..r0+3

        float acc[5][4];
        #pragma unroll
        for (int ch = 0; ch < 5; ch++) {
            float s0 = 0.f, s1 = 0.f, s2 = 0.f, s3 = 0.f;
            #pragma unroll
            for (int j = 0; j < 14; j++) {
                const float v = hs[ch][r0 + j][c];
                if (j <= 10)            s0 = fmaf(v, gw(j),     s0);
                if (j >= 1 && j <= 11)  s1 = fmaf(v, gw(j - 1), s1);
                if (j >= 2 && j <= 12)  s2 = fmaf(v, gw(j - 2), s2);
                if (j >= 3)             s3 = fmaf(v, gw(j - 3), s3);
            }
            acc[ch][0] = s0; acc[ch][1] = s1; acc[ch][2] = s2; acc[ch][3] = s3;
        }

        const float C1 = 6.5025f;    // (0.01*255)^2
        const float C2 = 58.5225f;   // (0.03*255)^2
        const float SCALE = 0.000244140625f;  // 2^-12: keep 4-products in range

        float nn[4], dd[4];
        #pragma unroll
        for (int o = 0; o < 4; o++) {
            if (by + r0 + o < H && bx + c < W) {
                const float mu1 = acc[0][o], mu2 = acc[1][o];
                const float exx = acc[2][o], eyy = acc[3][o], exy = acc[4][o];
                const float m11 = mu1 * mu1;
                const float m22 = mu2 * mu2;
                const float m12 = mu1 * mu2;
                const float s1q = exx - m11;
                const float s2q = eyy - m22;
                const float s12 = exy - m12;
                nn[o] = ((2.f * m12 + C1) * SCALE) * ((2.f * s12 + C2) * SCALE);
                dd[o] = ((m11 + m22 + C1) * SCALE) * ((s1q + s2q + C2) * SCALE);
            } else {
                nn[o] = 0.f;
                dd[o] = 1.f;
            }
        }
        // sum_i n_i/d_i = (sum_i n_i * prod_{j!=i} d_j) / prod_j d_j  -> one RCP / 4 px
        const float d01 = dd[0] * dd[1];
        const float d23 = dd[2] * dd[3];
        const float D   = d01 * d23;
        const float s01 = fmaf(nn[0], dd[1], nn[1] * dd[0]);   // over d01
        const float s23 = fmaf(nn[2], dd[3], nn[3] * dd[2]);   // over d23
        const float S   = fmaf(s01, d23, s23 * d01);
        lsum = __fdividef(S, D);
    }

    // ---------------- block reduction ----------------
    #pragma unroll
    for (int off = 16; off; off >>= 1)
        lsum += __shfl_xor_sync(0xffffffffu, lsum, off);
    if ((tid & 31) == 0) wsum[tid >> 5] = lsum;
    __syncthreads();
    if (tid == 0) {
        float s = 0.f;
        #pragma unroll
        for (int w = 0; w < NTHREADS / 32; w++) s += wsum[w];
        g_blockSums[blockIdx.y * gridDim.x + blockIdx.x] = s;
        __threadfence();
        unsigned int prev = atomicAdd(&g_count, 1u);
        isLast = (prev == (unsigned int)(nBlocks - 1));
    }
    __syncthreads();

    // ---------------- last block: final deterministic reduce ----------------
    if (isLast) {
        double acc = 0.0;
        if ((nBlocks & 3) == 0) {
            const float4* p = (const float4*)g_blockSums;
            const int n4 = nBlocks >> 2;
            for (int i = tid; i < n4; i += NTHREADS) {
                float4 v = p[i];
                acc += (double)v.x + (double)v.y + (double)v.z + (double)v.w;
            }
        } else {
            for (int i = tid; i < nBlocks; i += NTHREADS)
                acc += (double)g_blockSums[i];
        }
        __shared__ double dsm[NTHREADS];
        dsm[tid] = acc;
        __syncthreads();
        #pragma unroll
        for (int s = NTHREADS / 2; s; s >>= 1) {
            if (tid < s) dsm[tid] += dsm[tid + s];
            __syncthreads();
        }
        if (tid == 0) {
            out[0] = (float)(dsm[0] * inv_n);
            g_count = 0;   // reset for next graph replay (deterministic)
        }
    }
}

extern "C" void kernel_launch(void* const* d_in, const int* in_sizes, int n_in,
                              void* d_out, int out_size)
{
    (void)n_in; (void)out_size;
    const float* img1 = (const float*)d_in[0];
    const float* img2 = (const float*)d_in[1];

    const long long n = (long long)in_sizes[0];
    int W = (int)(sqrt((double)n) + 0.5);
    if (W <= 0) W = 1;
    int H = (int)(n / W);

    dim3 grid((W + TILE - 1) / TILE, (H + TILE - 1) / TILE);
    const int nb = (int)(grid.x * grid.y);
    const double inv_n = 1.0 / ((double)H * (double)W);
    ssim_tile_kernel<<<grid, NTHREADS>>>(img1, img2, W, H, nb, inv_n,
                                         (float*)d_out);
}

// round 3
// speedup vs baseline: 1.1156x; 1.0694x over previous
#include <cuda_runtime.h>
#include <math.h>

#define TILE      32
#define HALO      5
#define RAW       (TILE + 2*HALO)   /* 42 */
#define RAWP      43                /* odd pitch -> conflict-free horizontal reads */
#define HP        33                /* pitch for scalar intermediate array        */
#define HP2       33                /* pitch for packed (u64) intermediate arrays */
#define NTHREADS  256

typedef unsigned long long u64;

// Per-block partial sums (deterministic: each block writes exactly one slot).
__device__ float g_blockSums[65536];
__device__ unsigned int g_count = 0;

// Normalized 1D Gaussian, size 11, sigma 1.5 (matches cv2.getGaussianKernel).
__device__ __forceinline__ float gw(int t) {
    constexpr float G[11] = {
        0.00102838f, 0.00759876f, 0.03600077f, 0.10936069f, 0.21300553f,
        0.26601172f,
        0.21300553f, 0.10936069f, 0.03600077f, 0.00759876f, 0.00102838f };
    return G[t];
}
// index of unique weight (kernel symmetric): 0..5
__device__ __forceinline__ int wux(int t) { return t <= 5 ? t : 10 - t; }

// ---- packed f32x2 helpers (Blackwell) ----
__device__ __forceinline__ u64 pack2(float lo, float hi) {
    u64 r; asm("mov.b64 %0, {%1, %2};" : "=l"(r) : "f"(lo), "f"(hi)); return r;
}
__device__ __forceinline__ void unpack2(u64 v, float& lo, float& hi) {
    asm("mov.b64 {%0, %1}, %2;" : "=f"(lo), "=f"(hi) : "l"(v));
}
__device__ __forceinline__ u64 mul2(u64 a, u64 b) {
    u64 d; asm("mul.rn.f32x2 %0, %1, %2;" : "=l"(d) : "l"(a), "l"(b)); return d;
}
__device__ __forceinline__ u64 fma2(u64 a, u64 b, u64 c) {
    u64 d; asm("fma.rn.f32x2 %0, %1, %2, %3;" : "=l"(d) : "l"(a), "l"(b), "l"(c)); return d;
}

__global__ __launch_bounds__(NTHREADS)
void ssim_tile_kernel(const float* __restrict__ img1,
                      const float* __restrict__ img2,
                      int W, int H, int nBlocks, double inv_n,
                      float* __restrict__ out)
{
    __shared__ float sx[RAW][RAWP];
    __shared__ float sy[RAW][RAWP];
    __shared__ u64   hs_mu[RAW][HP2];   // packed (hblur(x),  hblur(y))
    __shared__ u64   hs_sq[RAW][HP2];   // packed (hblur(xx), hblur(yy))
    __shared__ float hs_xy[RAW][HP];    // hblur(xy)
    __shared__ float wsum[NTHREADS / 32];
    __shared__ bool  isLast;

    const int tid = threadIdx.x;
    const int bx = blockIdx.x * TILE;
    const int by = blockIdx.y * TILE;

    // packed duplicated Gaussian weights (6 unique values), hoisted in regs
    u64 GW2[6];
    #pragma unroll
    for (int t = 0; t < 6; t++) GW2[t] = pack2(gw(t), gw(t));

    // ---------------- load raw tile with replicate ("edge") padding ----------------
    for (int i = tid; i < RAW * RAW; i += NTHREADS) {
        int r = i / RAW;
        int c = i - r * RAW;
        int gy = by - HALO + r; gy = gy < 0 ? 0 : (gy >= H ? H - 1 : gy);
        int gx = bx - HALO + c; gx = gx < 0 ? 0 : (gx >= W ? W - 1 : gx);
        size_t idx = (size_t)gy * (size_t)W + (size_t)gx;
        sx[r][c] = img1[idx];
        sy[r][c] = img2[idx];
    }
    __syncthreads();

    // ---------------- horizontal pass: 42 rows x 8 groups of 4 output cols ----------
    for (int i = tid; i < RAW * 8; i += NTHREADS) {
        const int r = i >> 3;
        const int g = (i & 7) * 4;

        u64   amu[4] = {0ull, 0ull, 0ull, 0ull};
        u64   asq[4] = {0ull, 0ull, 0ull, 0ull};
        float axy[4] = {0.f, 0.f, 0.f, 0.f};

        #pragma unroll
        for (int k = 0; k < 14; k++) {
            const float vx = sx[r][g + k];
            const float vy = sy[r][g + k];
            const u64   v2  = pack2(vx, vy);
            const u64   sq2 = mul2(v2, v2);
            const float xy  = vx * vy;
            #pragma unroll
            for (int o = 0; o < 4; o++) {
                const int t = k - o;
                if (t >= 0 && t < 11) {
                    amu[o] = fma2(v2,  GW2[wux(t)], amu[o]);
                    asq[o] = fma2(sq2, GW2[wux(t)], asq[o]);
                    axy[o] = fmaf(xy, gw(t), axy[o]);
                }
            }
        }
        #pragma unroll
        for (int o = 0; o < 4; o++) {
            hs_mu[r][g + o] = amu[o];
            hs_sq[r][g + o] = asq[o];
            hs_xy[r][g + o] = axy[o];
        }
    }
    __syncthreads();

    // ---------------- vertical pass + SSIM: 32 cols x 8 row-groups of 4 rows --------
    float lsum = 0.f;
    {
        const int c  = tid & 31;
        const int r0 = (tid >> 5) * 4;   // output rows r0..r0+3

        u64   vmu[4] = {0ull, 0ull, 0ull, 0ull};
        u64   vsq[4] = {0ull, 0ull, 0ull, 0ull};
        float vxy[4] = {0.f, 0.f, 0.f, 0.f};

        #pragma unroll
        for (int j = 0; j < 14; j++) {
            const u64   m = hs_mu[r0 + j][c];
            const u64   s = hs_sq[r0 + j][c];
            const float p = hs_xy[r0 + j][c];
            #pragma unroll
            for (int o = 0; o < 4; o++) {
                const int t = j - o;
                if (t >= 0 && t < 11) {
                    vmu[o] = fma2(m, GW2[wux(t)], vmu[o]);
                    vsq[o] = fma2(s, GW2[wux(t)], vsq[o]);
                    vxy[o] = fmaf(p, gw(t), vxy[o]);
                }
            }
        }

        const float C1 = 6.5025f;    // (0.01*255)^2
        const float C2 = 58.5225f;   // (0.03*255)^2
        const float SCALE = 0.000244140625f;  // 2^-12: keep 4-products in range

        float nn[4], dd[4];
        #pragma unroll
        for (int o = 0; o < 4; o++) {
            if (by + r0 + o < H && bx + c < W) {
                float mu1, mu2, exx, eyy;
                unpack2(vmu[o], mu1, mu2);
                unpack2(vsq[o], exx, eyy);
                const float exy = vxy[o];
                const float m11 = mu1 * mu1;
                const float m22 = mu2 * mu2;
                const float m12 = mu1 * mu2;
                const float s1q = exx - m11;
                const float s2q = eyy - m22;
                const float s12 = exy - m12;
                nn[o] = ((2.f * m12 + C1) * SCALE) * ((2.f * s12 + C2) * SCALE);
                dd[o] = ((m11 + m22 + C1) * SCALE) * ((s1q + s2q + C2) * SCALE);
            } else {
                nn[o] = 0.f;
                dd[o] = 1.f;
            }
        }
        // sum_i n_i/d_i = (sum_i n_i * prod_{j!=i} d_j) / prod_j d_j  -> one RCP / 4 px
        const float d01 = dd[0] * dd[1];
        const float d23 = dd[2] * dd[3];
        const float D   = d01 * d23;
        const float s01 = fmaf(nn[0], dd[1], nn[1] * dd[0]);
        const float s23 = fmaf(nn[2], dd[3], nn[3] * dd[2]);
        const float S   = fmaf(s01, d23, s23 * d01);
        lsum = __fdividef(S, D);
    }

    // ---------------- block reduction ----------------
    #pragma unroll
    for (int off = 16; off; off >>= 1)
        lsum += __shfl_xor_sync(0xffffffffu, lsum, off);
    if ((tid & 31) == 0) wsum[tid >> 5] = lsum;
    __syncthreads();
    if (tid == 0) {
        float s = 0.f;
        #pragma unroll
        for (int w = 0; w < NTHREADS / 32; w++) s += wsum[w];
        g_blockSums[blockIdx.y * gridDim.x + blockIdx.x] = s;
        __threadfence();
        unsigned int prev = atomicAdd(&g_count, 1u);
        isLast = (prev == (unsigned int)(nBlocks - 1));
    }
    __syncthreads();

    // ---------------- last block: final deterministic reduce ----------------
    if (isLast) {
        double acc = 0.0;
        if ((nBlocks & 3) == 0) {
            const float4* p = (const float4*)g_blockSums;
            const int n4 = nBlocks >> 2;
            for (int i = tid; i < n4; i += NTHREADS) {
                float4 v = p[i];
                acc += (double)v.x + (double)v.y + (double)v.z + (double)v.w;
            }
        } else {
            for (int i = tid; i < nBlocks; i += NTHREADS)
                acc += (double)g_blockSums[i];
        }
        __shared__ double dsm[NTHREADS];
        dsm[tid] = acc;
        __syncthreads();
        #pragma unroll
        for (int s = NTHREADS / 2; s; s >>= 1) {
            if (tid < s) dsm[tid] += dsm[tid + s];
            __syncthreads();
        }
        if (tid == 0) {
            out[0] = (float)(dsm[0] * inv_n);
            g_count = 0;   // reset for next graph replay (deterministic)
        }
    }
}

extern "C" void kernel_launch(void* const* d_in, const int* in_sizes, int n_in,
                              void* d_out, int out_size)
{
    (void)n_in; (void)out_size;
    const float* img1 = (const float*)d_in[0];
    const float* img2 = (const float*)d_in[1];

    const long long n = (long long)in_sizes[0];
    int W = (int)(sqrt((double)n) + 0.5);
    if (W <= 0) W = 1;
    int H = (int)(n / W);

    dim3 grid((W + TILE - 1) / TILE, (H + TILE - 1) / TILE);
    const int nb = (int)(grid.x * grid.y);
    const double inv_n = 1.0 / ((double)H * (double)W);
    ssim_tile_kernel<<<grid, NTHREADS>>>(img1, img2, W, H, nb, inv_n,
                                         (float*)d_out);
}